// round 1
// baseline (speedup 1.0000x reference)
#include <cuda_runtime.h>
#include <cstdint>

// AttentionLayer: B=2048, N=64, D=256, H=16
//   m_i[h]  = sum_d members[b,i,d]*item[b,d]*W1[d,h]
//   s[h]    = sum_i m_i[h]
//   pre     = 64*m_i[h] - s[h] + b1[h] ; relu ; logit_i = sum_h relu*W2[h] + b2
//   out[b,i] = softmax_i(logit)

constexpr int Bb = 2048;
constexpr int Nn = 64;
constexpr int Dd = 256;
constexpr int Hh = 16;
constexpr int WPB = 4;                 // warps (=batches) per block
constexpr int THREADS = WPB * 32;

#define FMA2(acc, a, w)  asm("fma.rn.f32x2 %0, %1, %2, %0;" : "+l"(acc) : "l"(a), "l"(w))
#define ADD2(d, a, b_)   asm("add.rn.f32x2 %0, %1, %2;" : "=l"(d) : "l"(a), "l"(b_))
#define PACK2(d, lo, hi) asm("mov.b64 %0, {%1, %2};" : "=l"(d) : "f"(lo), "f"(hi))
#define UNPACK2(lo, hi, v) asm("mov.b64 {%0, %1}, %2;" : "=f"(lo), "=f"(hi) : "l"(v))

__global__ __launch_bounds__(THREADS, 3)
void attn_kernel(const float* __restrict__ members,
                 const float* __restrict__ item,
                 const float* __restrict__ W1,
                 const float* __restrict__ b1,
                 const float* __restrict__ W2,
                 const float* __restrict__ b2,
                 float* __restrict__ out)
{
    __shared__ float4 W1s4[Dd * Hh / 4];           // 16 KB, block-shared
    __shared__ float4 itemS4[WPB][Dd / 4];         //  4 KB
    __shared__ float4 rowS4[WPB][2][Dd / 4];       //  8 KB (double-buffered row)
    __shared__ float  mS[WPB][Nn * (Hh + 1)];      // ~17 KB, stride 17 = conflict-free transpose
    __shared__ float  sS[WPB][Hh];                 // 256 B

    const int tid  = threadIdx.x;
    const int wid  = tid >> 5;
    const int lane = tid & 31;
    const int h    = lane & 15;     // head owned by this lane
    const int half = lane >> 4;     // which interleaved d-quads this lane owns
    const int b    = blockIdx.x * WPB + wid;

    // ---- stage W1 (block-wide, coalesced) ----
    {
        const float4* g = (const float4*)W1;
        #pragma unroll
        for (int k = 0; k < (Dd * Hh / 4) / THREADS; k++)
            W1s4[tid + k * THREADS] = g[tid + k * THREADS];
    }
    // ---- stage item for this warp's batch ----
    {
        const float4* g = (const float4*)(item + (size_t)b * Dd);
        itemS4[wid][lane]      = g[lane];
        itemS4[wid][lane + 32] = g[lane + 32];
    }
    __syncthreads();

    const float* W1s = (const float*)W1s4;
    const float* itS = (const float*)itemS4[wid];

    // ---- build register-resident packed weights: w[d] = W1[d][h] * item[d] ----
    // Lane owns quads q = 2j + half (j = 0..31) -> 128 d-values -> 64 f32x2 pairs.
    unsigned long long wreg[64];
    #pragma unroll
    for (int j = 0; j < 32; j++) {
        const int d0 = (2 * j + half) * 4;
        #pragma unroll
        for (int p = 0; p < 2; p++) {
            float w0 = W1s[(d0 + 2 * p)     * Hh + h] * itS[d0 + 2 * p];
            float w1 = W1s[(d0 + 2 * p + 1) * Hh + h] * itS[d0 + 2 * p + 1];
            PACK2(wreg[2 * j + p], w0, w1);
        }
    }

    // ---- main loop over member rows ----
    const float4* grow = (const float4*)(members + (size_t)b * Nn * Dd);
    float4 pv0 = grow[lane];
    float4 pv1 = grow[lane + 32];
    float s_h = 0.f;

    for (int r = 0; r < Nn; r++) {
        const int buf = r & 1;
        rowS4[wid][buf][lane]      = pv0;
        rowS4[wid][buf][lane + 32] = pv1;
        __syncwarp();
        if (r + 1 < Nn) {                       // prefetch next row (overlaps compute)
            const float4* gn = grow + (r + 1) * (Dd / 4);
            pv0 = gn[lane];
            pv1 = gn[lane + 32];
        }

        const ulonglong2* rb = (const ulonglong2*)rowS4[wid][buf];
        unsigned long long ax0 = 0ull, ax1 = 0ull, ay0 = 0ull, ay1 = 0ull;
        #pragma unroll
        for (int j = 0; j < 32; j++) {
            ulonglong2 a = rb[2 * j + half];    // broadcast LDS.128, 2 distinct addrs, adjacent banks
            if (j & 1) { FMA2(ax1, a.x, wreg[2 * j]); FMA2(ay1, a.y, wreg[2 * j + 1]); }
            else       { FMA2(ax0, a.x, wreg[2 * j]); FMA2(ay0, a.y, wreg[2 * j + 1]); }
        }
        unsigned long long t0, t1;
        ADD2(t0, ax0, ax1);
        ADD2(t1, ay0, ay1);
        ADD2(t0, t0, t1);
        float lo, hi;
        UNPACK2(lo, hi, t0);
        float macc = lo + hi;
        macc += __shfl_xor_sync(0xffffffffu, macc, 16);   // combine the two d-halves
        s_h += macc;
        if (half == 0) mS[wid][r * (Hh + 1) + h] = macc;
    }

    if (lane < 16) sS[wid][lane] = s_h;
    __syncwarp();

    // ---- epilogue: 2 rows per lane, no shuffles in the MLP part ----
    float c[16], w2r[16];
    const float b2v = __ldg(b2);
    #pragma unroll
    for (int hh = 0; hh < 16; hh++) {
        c[hh]   = __ldg(&b1[hh]) - sS[wid][hh];
        w2r[hh] = __ldg(&W2[hh]);
    }

    float logit0 = b2v, logit1 = b2v;
    #pragma unroll
    for (int hh = 0; hh < 16; hh++) {
        float p0 = 64.f * mS[wid][lane        * (Hh + 1) + hh] + c[hh];
        float p1 = 64.f * mS[wid][(lane + 32) * (Hh + 1) + hh] + c[hh];
        logit0 += fmaxf(p0, 0.f) * w2r[hh];
        logit1 += fmaxf(p1, 0.f) * w2r[hh];
    }

    // ---- warp softmax over 64 rows (2 per lane) ----
    float mx = fmaxf(logit0, logit1);
    #pragma unroll
    for (int o = 16; o >= 1; o >>= 1)
        mx = fmaxf(mx, __shfl_xor_sync(0xffffffffu, mx, o));
    float e0 = __expf(logit0 - mx);
    float e1 = __expf(logit1 - mx);
    float sm = e0 + e1;
    #pragma unroll
    for (int o = 16; o >= 1; o >>= 1)
        sm += __shfl_xor_sync(0xffffffffu, sm, o);
    const float inv = 1.0f / sm;

    out[(size_t)b * Nn + lane]      = e0 * inv;
    out[(size_t)b * Nn + lane + 32] = e1 * inv;
}

extern "C" void kernel_launch(void* const* d_in, const int* in_sizes, int n_in,
                              void* d_out, int out_size)
{
    attn_kernel<<<Bb / WPB, THREADS>>>(
        (const float*)d_in[0],   // members_embeds [2048,64,256]
        (const float*)d_in[1],   // item_embeds    [2048,256]
        (const float*)d_in[2],   // W1 [256,16]
        (const float*)d_in[3],   // b1 [16]
        (const float*)d_in[4],   // W2 [16,1]
        (const float*)d_in[5],   // b2 [1]
        (float*)d_out);          // out [2048,64]
}

// round 2
// speedup vs baseline: 1.7449x; 1.7449x over previous
#include <cuda_runtime.h>
#include <cstdint>

// AttentionLayer: B=2048, N=64, D=256, H=16
//   m_i[h]  = sum_d members[b,i,d]*item[b,d]*W1[d,h]
//   s[h]    = sum_i m_i[h]
//   pre     = 64*m_i[h] - s[h] + b1[h] ; relu ; logit_i = sum_h relu*W2[h] + b2
//   out[b,i] = softmax_i(logit)
//
// R2: cp.async 8-deep row ring (7 rows/warp in flight), no block-wide smem
// staging, no __syncthreads. Warp-per-batch, lane owns (h = lane&15,
// half = lane>>4) with interleaved d-quads; weights register-resident as f32x2.

constexpr int Bb = 2048;
constexpr int Nn = 64;
constexpr int Dd = 256;
constexpr int Hh = 16;
constexpr int WPB = 4;                 // warps (=batches) per block
constexpr int THREADS = WPB * 32;
constexpr int RING = 8;                // row ring depth (smem), 7 rows in flight

#define FMA2(acc, a, w)  asm("fma.rn.f32x2 %0, %1, %2, %0;" : "+l"(acc) : "l"(a), "l"(w))
#define ADD2(d, a, b_)   asm("add.rn.f32x2 %0, %1, %2;" : "=l"(d) : "l"(a), "l"(b_))
#define PACK2(d, lo, hi) asm("mov.b64 %0, {%1, %2};" : "=l"(d) : "f"(lo), "f"(hi))
#define UNPACK2(lo, hi, v) asm("mov.b64 {%0, %1}, %2;" : "=f"(lo), "=f"(hi) : "l"(v))

__device__ __forceinline__ uint32_t smem_u32(const void* p) {
    uint32_t a;
    asm("{ .reg .u64 t; cvta.to.shared.u64 t, %1; cvt.u32.u64 %0, t; }"
        : "=r"(a) : "l"(p));
    return a;
}
__device__ __forceinline__ void cp_async16(uint32_t dst, const void* src) {
    asm volatile("cp.async.cg.shared.global [%0], [%1], 16;" :: "r"(dst), "l"(src));
}
__device__ __forceinline__ void cp_commit() {
    asm volatile("cp.async.commit_group;" ::: "memory");
}
__device__ __forceinline__ void cp_wait7() {
    asm volatile("cp.async.wait_group %0;" :: "n"(RING - 1) : "memory");
}

__global__ __launch_bounds__(THREADS, 3)
void attn_kernel(const float* __restrict__ members,
                 const float* __restrict__ item,
                 const float* __restrict__ W1,
                 const float* __restrict__ b1,
                 const float* __restrict__ W2,
                 const float* __restrict__ b2,
                 float* __restrict__ out)
{
    __shared__ float4 rowS4[WPB][RING][Dd / 4];    // 32 KB: 8-deep row ring per warp
    __shared__ float  mS[WPB][Nn * (Hh + 1)];      // ~17 KB, stride 17 transpose
    __shared__ float  sS[WPB][Hh];

    const int tid  = threadIdx.x;
    const int wid  = tid >> 5;
    const int lane = tid & 31;
    const int h    = lane & 15;     // head owned by this lane
    const int half = lane >> 4;     // interleaved d-quad half owned by this lane
    const int b    = blockIdx.x * WPB + wid;

    const float4* grow = (const float4*)(members + (size_t)b * Nn * Dd);
    const uint32_t ringBase = smem_u32(&rowS4[wid][0][0]);
    const uint32_t dstOff   = lane * 16;            // this lane's first float4 slot

    // ---- prologue: put rows 0..RING-2 in flight ----
    #pragma unroll
    for (int r = 0; r < RING - 1; r++) {
        const float4* g = grow + r * (Dd / 4);
        uint32_t d0 = ringBase + r * (Dd * 4) + dstOff;
        cp_async16(d0,       g + lane);
        cp_async16(d0 + 512, g + lane + 32);
        cp_commit();
    }

    // ---- build register-resident packed weights: w[d] = W1[d][h]*item[b][d] ----
    // Lane owns quads q = 2j + half (j=0..31) -> 128 d -> 64 f32x2.
    const float* itG = item + (size_t)b * Dd;
    unsigned long long wreg[64];
    #pragma unroll
    for (int j = 0; j < 32; j++) {
        const int d0 = (2 * j + half) * 4;
        #pragma unroll
        for (int p = 0; p < 2; p++) {
            float w0 = __ldg(&W1[(d0 + 2 * p)     * Hh + h]) * __ldg(&itG[d0 + 2 * p]);
            float w1 = __ldg(&W1[(d0 + 2 * p + 1) * Hh + h]) * __ldg(&itG[d0 + 2 * p + 1]);
            PACK2(wreg[2 * j + p], w0, w1);
        }
    }

    // ---- main loop over member rows ----
    float s_h = 0.f;
    for (int r = 0; r < Nn; r++) {
        // keep the pipeline full: issue row r+RING-1, always commit (empty
        // groups at the tail keep wait_group arithmetic exact)
        if (r + RING - 1 < Nn) {
            const float4* g = grow + (r + RING - 1) * (Dd / 4);
            uint32_t d0 = ringBase + ((r + RING - 1) & (RING - 1)) * (Dd * 4) + dstOff;
            cp_async16(d0,       g + lane);
            cp_async16(d0 + 512, g + lane + 32);
        }
        cp_commit();
        cp_wait7();                     // all but newest RING-1 groups done => row r landed
        __syncwarp();

        const ulonglong2* rb = (const ulonglong2*)rowS4[wid][r & (RING - 1)];
        unsigned long long ax0 = 0ull, ax1 = 0ull, ay0 = 0ull, ay1 = 0ull;
        #pragma unroll
        for (int j = 0; j < 32; j++) {
            ulonglong2 a = rb[2 * j + half];     // broadcast LDS.128, 2 addrs, adjacent banks
            if (j & 1) { FMA2(ax1, a.x, wreg[2 * j]); FMA2(ay1, a.y, wreg[2 * j + 1]); }
            else       { FMA2(ax0, a.x, wreg[2 * j]); FMA2(ay0, a.y, wreg[2 * j + 1]); }
        }
        unsigned long long t0, t1;
        ADD2(t0, ax0, ax1);
        ADD2(t1, ay0, ay1);
        ADD2(t0, t0, t1);
        float lo, hi;
        UNPACK2(lo, hi, t0);
        float macc = lo + hi;
        macc += __shfl_xor_sync(0xffffffffu, macc, 16);   // combine the two d-halves
        s_h += macc;
        if (half == 0) mS[wid][r * (Hh + 1) + h] = macc;
        __syncwarp();                   // m visible + ring slot free before reuse
    }

    if (lane < 16) sS[wid][lane] = s_h;
    __syncwarp();

    // ---- epilogue: 2 rows per lane ----
    float c[16], w2r[16];
    const float b2v = __ldg(b2);
    #pragma unroll
    for (int hh = 0; hh < 16; hh++) {
        c[hh]   = __ldg(&b1[hh]) - sS[wid][hh];
        w2r[hh] = __ldg(&W2[hh]);
    }

    float logit0 = b2v, logit1 = b2v;
    #pragma unroll
    for (int hh = 0; hh < 16; hh++) {
        float p0 = 64.f * mS[wid][lane        * (Hh + 1) + hh] + c[hh];
        float p1 = 64.f * mS[wid][(lane + 32) * (Hh + 1) + hh] + c[hh];
        logit0 += fmaxf(p0, 0.f) * w2r[hh];
        logit1 += fmaxf(p1, 0.f) * w2r[hh];
    }

    // ---- warp softmax over 64 rows (2 per lane) ----
    float mx = fmaxf(logit0, logit1);
    #pragma unroll
    for (int o = 16; o >= 1; o >>= 1)
        mx = fmaxf(mx, __shfl_xor_sync(0xffffffffu, mx, o));
    float e0 = __expf(logit0 - mx);
    float e1 = __expf(logit1 - mx);
    float sm = e0 + e1;
    #pragma unroll
    for (int o = 16; o >= 1; o >>= 1)
        sm += __shfl_xor_sync(0xffffffffu, sm, o);
    const float inv = 1.0f / sm;

    out[(size_t)b * Nn + lane]      = e0 * inv;
    out[(size_t)b * Nn + lane + 32] = e1 * inv;
}

extern "C" void kernel_launch(void* const* d_in, const int* in_sizes, int n_in,
                              void* d_out, int out_size)
{
    attn_kernel<<<Bb / WPB, THREADS>>>(
        (const float*)d_in[0],   // members_embeds [2048,64,256]
        (const float*)d_in[1],   // item_embeds    [2048,256]
        (const float*)d_in[2],   // W1 [256,16]
        (const float*)d_in[3],   // b1 [16]
        (const float*)d_in[4],   // W2 [16,1]
        (const float*)d_in[5],   // b2 [1]
        (float*)d_out);          // out [2048,64]
}

// round 3
// speedup vs baseline: 2.1198x; 1.2149x over previous
#include <cuda_runtime.h>
#include <cstdint>

// AttentionLayer: B=2048, N=64, D=256, H=16
//   m_i[h]  = sum_d members[b,i,d]*item[b,d]*W1[d,h]
//   s[h]    = sum_i m_i[h] ; pre = 64*m_i - s + b1 ; relu ; logit = relu@W2 + b2
//   out[b,i] = softmax_i(logit)
//
// R3: 2 warps per batch (8 heads each, 4 lanes/head -> wreg 64 regs),
// 2 rows per iteration, shared cp.async ring per batch, one __syncthreads
// per iteration. 16 warps/SM guaranteed via launch_bounds(128,4).

constexpr int Bb = 2048;
constexpr int Nn = 64;
constexpr int Dd = 256;
constexpr int Hh = 16;
constexpr int BPB = 2;                 // batches per block
constexpr int THREADS = 128;           // 4 warps: 2 per batch
constexpr int RING = 4;                // ring of 4 iterations x 2 rows = 8 rows

#define FMA2(acc, a, w)  asm("fma.rn.f32x2 %0, %1, %2, %0;" : "+l"(acc) : "l"(a), "l"(w))
#define ADD2(d, a, b_)   asm("add.rn.f32x2 %0, %1, %2;" : "=l"(d) : "l"(a), "l"(b_))
#define PACK2(d, lo, hi) asm("mov.b64 %0, {%1, %2};" : "=l"(d) : "f"(lo), "f"(hi))
#define UNPACK2(lo, hi, v) asm("mov.b64 {%0, %1}, %2;" : "=f"(lo), "=f"(hi) : "l"(v))

__device__ __forceinline__ uint32_t smem_u32(const void* p) {
    uint32_t a;
    asm("{ .reg .u64 t; cvta.to.shared.u64 t, %1; cvt.u32.u64 %0, t; }"
        : "=r"(a) : "l"(p));
    return a;
}
__device__ __forceinline__ void cp_async16(uint32_t dst, const void* src) {
    asm volatile("cp.async.cg.shared.global [%0], [%1], 16;" :: "r"(dst), "l"(src));
}
__device__ __forceinline__ void cp_commit() {
    asm volatile("cp.async.commit_group;" ::: "memory");
}
__device__ __forceinline__ void cp_wait2() {
    asm volatile("cp.async.wait_group %0;" :: "n"(RING - 2) : "memory");
}

__global__ __launch_bounds__(THREADS, 4)
void attn_kernel(const float* __restrict__ members,
                 const float* __restrict__ item,
                 const float* __restrict__ W1,
                 const float* __restrict__ b1,
                 const float* __restrict__ W2,
                 const float* __restrict__ b2,
                 float* __restrict__ out)
{
    __shared__ float4 ring[BPB][RING][2][Dd / 4];  // 16 KB: 4-slot ring, 2 rows/slot
    __shared__ float  mS[BPB][Nn * (Hh + 1)];      // 8.7 KB, stride 17
    __shared__ float  sS[BPB][Hh];
    __shared__ float  red[BPB][2][2];              // [batch][max|sum][warp parity]

    const int tid  = threadIdx.x;
    const int wid  = tid >> 5;
    const int lane = tid & 31;
    const int bl   = wid >> 1;          // local batch (0..1)
    const int p    = wid & 1;           // warp parity: heads 8p..8p+7
    const int h    = (lane & 7) + 8 * p;
    const int q    = lane >> 3;         // d-quarter (0..3)
    const int b    = blockIdx.x * BPB + bl;

    const float4* grow = (const float4*)(members + (size_t)b * Nn * Dd);
    const uint32_t ringBase = smem_u32(&ring[bl][0][0][0]);
    const uint32_t dstOff   = p * 512 + lane * 16; // this warp covers half of each row

    // ---- prologue: iterations 0..2 (rows 0..5) in flight, 1 group each ----
    #pragma unroll
    for (int it = 0; it < RING - 1; it++) {
        #pragma unroll
        for (int rr = 0; rr < 2; rr++) {
            const int r = 2 * it + rr;
            cp_async16(ringBase + it * 2048 + rr * 1024 + dstOff,
                       grow + r * (Dd / 4) + p * 32 + lane);
        }
        cp_commit();
    }

    // ---- register weights: w[d] = W1[d][h]*item[b][d] for this lane's 64 d's ----
    // lane owns quads j = 4t + q (t = 0..15) -> 64 floats -> 32 f32x2
    const float* itG = item + (size_t)b * Dd;
    unsigned long long wreg[32];
    #pragma unroll
    for (int t = 0; t < 16; t++) {
        const int d0 = (4 * t + q) * 4;
        float w0 = __ldg(&W1[(d0 + 0) * Hh + h]) * __ldg(&itG[d0 + 0]);
        float w1 = __ldg(&W1[(d0 + 1) * Hh + h]) * __ldg(&itG[d0 + 1]);
        float w2 = __ldg(&W1[(d0 + 2) * Hh + h]) * __ldg(&itG[d0 + 2]);
        float w3 = __ldg(&W1[(d0 + 3) * Hh + h]) * __ldg(&itG[d0 + 3]);
        PACK2(wreg[2 * t],     w0, w1);
        PACK2(wreg[2 * t + 1], w2, w3);
    }

    // ---- main loop: 32 iterations x 2 rows ----
    float s_h = 0.f;
    for (int i = 0; i < Nn / 2; i++) {
        cp_wait2();                 // group i complete (<=2 newer outstanding)
        __syncthreads();            // cross-warp visibility + ring slot (i-1) free

        // refill: issue iteration i+3 into slot (i+3)&3 (safe after the bar)
        if (i + RING - 1 < Nn / 2) {
            const int it = i + RING - 1;
            #pragma unroll
            for (int rr = 0; rr < 2; rr++) {
                const int r = 2 * it + rr;
                cp_async16(ringBase + (it & (RING - 1)) * 2048 + rr * 1024 + dstOff,
                           grow + r * (Dd / 4) + p * 32 + lane);
            }
        }
        cp_commit();                // always commit (keeps wait arithmetic exact)

        const ulonglong2* ra = (const ulonglong2*)&ring[bl][i & (RING - 1)][0][0];
        const ulonglong2* rbp = ra + 64;   // second row of the slot

        unsigned long long aA[4] = {0ull,0ull,0ull,0ull};
        unsigned long long aB[4] = {0ull,0ull,0ull,0ull};
        #pragma unroll
        for (int t = 0; t < 16; t++) {
            ulonglong2 va = ra[4 * t + q];   // broadcast LDS.128, 4 addrs, 64B apart
            ulonglong2 vb = rbp[4 * t + q];
            FMA2(aA[(2 * t)     & 3], va.x, wreg[2 * t]);
            FMA2(aA[(2 * t + 1) & 3], va.y, wreg[2 * t + 1]);
            FMA2(aB[(2 * t)     & 3], vb.x, wreg[2 * t]);
            FMA2(aB[(2 * t + 1) & 3], vb.y, wreg[2 * t + 1]);
        }
        unsigned long long tA0, tA1, tB0, tB1;
        ADD2(tA0, aA[0], aA[1]);  ADD2(tA1, aA[2], aA[3]);  ADD2(tA0, tA0, tA1);
        ADD2(tB0, aB[0], aB[1]);  ADD2(tB1, aB[2], aB[3]);  ADD2(tB0, tB0, tB1);
        float la, ha, lb, hb;
        UNPACK2(la, ha, tA0);
        UNPACK2(lb, hb, tB0);
        float mA = la + ha;
        float mB = lb + hb;
        // reduce over the 4 lanes sharing this head (xor 8, then 16)
        mA += __shfl_xor_sync(0xffffffffu, mA, 8);
        mB += __shfl_xor_sync(0xffffffffu, mB, 8);
        mA += __shfl_xor_sync(0xffffffffu, mA, 16);
        mB += __shfl_xor_sync(0xffffffffu, mB, 16);
        s_h += mA + mB;
        if (lane < 8) {
            mS[bl][(2 * i)     * (Hh + 1) + h] = mA;
            mS[bl][(2 * i + 1) * (Hh + 1) + h] = mB;
        }
    }

    if (lane < 8) sS[bl][h] = s_h;
    __syncthreads();                // mS + sS complete across both warps

    // ---- epilogue: each warp handles 32 rows (1 per lane) ----
    const int row = p * 32 + lane;
    const float b2v = __ldg(b2);
    float logit = b2v;
    #pragma unroll
    for (int hh = 0; hh < 16; hh++) {
        const float c   = __ldg(&b1[hh]) - sS[bl][hh];
        const float w2r = __ldg(&W2[hh]);
        const float pre = 64.f * mS[bl][row * (Hh + 1) + hh] + c;
        logit += fmaxf(pre, 0.f) * w2r;
    }

    // softmax over 64 rows spanning the 2 warps of this batch
    float mx = logit;
    #pragma unroll
    for (int o = 16; o >= 1; o >>= 1)
        mx = fmaxf(mx, __shfl_xor_sync(0xffffffffu, mx, o));
    if (lane == 0) red[bl][0][p] = mx;
    __syncthreads();
    const float mxAll = fmaxf(red[bl][0][0], red[bl][0][1]);

    const float e = __expf(logit - mxAll);
    float sm = e;
    #pragma unroll
    for (int o = 16; o >= 1; o >>= 1)
        sm += __shfl_xor_sync(0xffffffffu, sm, o);
    if (lane == 0) red[bl][1][p] = sm;
    __syncthreads();
    const float inv = 1.0f / (red[bl][1][0] + red[bl][1][1]);

    out[(size_t)b * Nn + row] = e * inv;
}

extern "C" void kernel_launch(void* const* d_in, const int* in_sizes, int n_in,
                              void* d_out, int out_size)
{
    attn_kernel<<<Bb / BPB, THREADS>>>(
        (const float*)d_in[0],   // members_embeds [2048,64,256]
        (const float*)d_in[1],   // item_embeds    [2048,256]
        (const float*)d_in[2],   // W1 [256,16]
        (const float*)d_in[3],   // b1 [16]
        (const float*)d_in[4],   // W2 [16,1]
        (const float*)d_in[5],   // b2 [1]
        (float*)d_out);          // out [2048,64]
}